// round 1
// baseline (speedup 1.0000x reference)
#include <cuda_runtime.h>
#include <math.h>

#define BB 2
#define NN 50000
#define DD 128
#define EE 800000
#define ROWS (BB*NN)          // 100000
#define TOT  (BB*NN*DD)       // 12,800,000 floats

// Scratch: message buffer and aggregation buffer (51.2 MB each).
__device__ float g_m[TOT];
__device__ float g_agg[TOT];
__device__ int   g_idx64;

// ---------------------------------------------------------------------------
// Detect whether src indices are int64 or int32 (values < 50000, so for int64
// little-endian storage every odd 32-bit word is zero; for random int32 data
// the chance of 64 consecutive odd-word zeros is ~0).
// ---------------------------------------------------------------------------
__global__ void detect_kernel(const int* __restrict__ src_words) {
    int is64 = 1;
    #pragma unroll 1
    for (int i = 0; i < 64; i++) {
        if (src_words[2 * i + 1] != 0) { is64 = 0; break; }
    }
    g_idx64 = is64;
}

// ---------------------------------------------------------------------------
// Zero the aggregation buffer (float4 grid-stride).
// ---------------------------------------------------------------------------
__global__ void zero_kernel() {
    int i = blockIdx.x * blockDim.x + threadIdx.x;
    float4* p = reinterpret_cast<float4*>(g_agg);
    if (i < TOT / 4) p[i] = make_float4(0.f, 0.f, 0.f, 0.f);
}

// ---------------------------------------------------------------------------
// GEMM: m[r, :] = H[r, :] @ W   (r over B*N flattened rows, K = D = 128)
// Block: 256 threads, 64 rows x 128 cols per block.
//   - H tile (64x128 fp32 = 32 KB) staged in smem; within a warp all lanes
//     read the same H element -> broadcast, conflict-free.
//   - W read as float4 LDG (64 KB, L1-resident after first pass).
// Thread t: warp w = t/32 owns rows [w*8, w*8+8), lane c = t%32 owns cols
// [4c, 4c+4). 32 FFMA + 8 LDS + 1 LDG.128 per k-iter.
// ---------------------------------------------------------------------------
__global__ void __launch_bounds__(256) gemm_kernel(
    const float* __restrict__ H, const float* __restrict__ W)
{
    __shared__ float shH[64][128];
    const int row0 = blockIdx.x * 64;
    const int t = threadIdx.x;

    // Load H tile: 2048 float4, 8 per thread, coalesced.
    #pragma unroll
    for (int i = t; i < 64 * 32; i += 256) {
        int r = i >> 5, c4 = i & 31;
        int gr = row0 + r;
        float4 v = (gr < ROWS) ? reinterpret_cast<const float4*>(H)[(size_t)gr * 32 + c4]
                               : make_float4(0.f, 0.f, 0.f, 0.f);
        reinterpret_cast<float4*>(&shH[r][0])[c4] = v;
    }
    __syncthreads();

    const int cg = t & 31;   // col group (4 cols)
    const int rg = t >> 5;   // row group (8 rows)

    float4 acc[8];
    #pragma unroll
    for (int r = 0; r < 8; r++) acc[r] = make_float4(0.f, 0.f, 0.f, 0.f);

    const float4* W4 = reinterpret_cast<const float4*>(W);
    #pragma unroll 4
    for (int k = 0; k < 128; k++) {
        float4 w = W4[k * 32 + cg];
        #pragma unroll
        for (int r = 0; r < 8; r++) {
            float h = shH[rg * 8 + r][k];
            acc[r].x = fmaf(h, w.x, acc[r].x);
            acc[r].y = fmaf(h, w.y, acc[r].y);
            acc[r].z = fmaf(h, w.z, acc[r].z);
            acc[r].w = fmaf(h, w.w, acc[r].w);
        }
    }

    #pragma unroll
    for (int r = 0; r < 8; r++) {
        int gr = row0 + rg * 8 + r;
        if (gr < ROWS)
            reinterpret_cast<float4*>(g_m)[(size_t)gr * 32 + cg] = acc[r];
    }
}

// ---------------------------------------------------------------------------
// Scatter: warp per edge; each warp handles both batches.
//   agg[b, dst[e], :] += m[b, src[e], :]
// 32 lanes x float4 covers D=128. Vector atomics (red.global.add.v4.f32).
// ---------------------------------------------------------------------------
__global__ void __launch_bounds__(256) scatter_kernel(
    const void* __restrict__ srcp, const void* __restrict__ dstp)
{
    int e = blockIdx.x * 8 + (threadIdx.x >> 5);
    if (e >= EE) return;
    const int lane = threadIdx.x & 31;

    long long s, d;
    if (g_idx64) {
        s = reinterpret_cast<const long long*>(srcp)[e];
        d = reinterpret_cast<const long long*>(dstp)[e];
    } else {
        s = reinterpret_cast<const int*>(srcp)[e];
        d = reinterpret_cast<const int*>(dstp)[e];
    }

    #pragma unroll
    for (int b = 0; b < BB; b++) {
        const float4 v = reinterpret_cast<const float4*>(
            g_m + (size_t)b * NN * DD + (size_t)s * DD)[lane];
        float* dp = g_agg + (size_t)b * NN * DD + (size_t)d * DD + lane * 4;
        asm volatile("red.global.add.v4.f32 [%0], {%1,%2,%3,%4};"
                     :: "l"(dp), "f"(v.x), "f"(v.y), "f"(v.z), "f"(v.w)
                     : "memory");
    }
}

// ---------------------------------------------------------------------------
// Epilogue: x = H + gelu(agg) (exact gelu, erf), LayerNorm over D=128.
// Warp per row, float4 per lane, shuffle reduction.
// ---------------------------------------------------------------------------
__device__ __forceinline__ float gelu_exact(float v) {
    return 0.5f * v * (1.0f + erff(v * 0.70710678118654752f));
}

__global__ void __launch_bounds__(256) ln_kernel(
    const float* __restrict__ Hin,
    const float* __restrict__ gamma, const float* __restrict__ beta,
    float* __restrict__ out)
{
    int row = blockIdx.x * 8 + (threadIdx.x >> 5);
    if (row >= ROWS) return;
    const int lane = threadIdx.x & 31;

    float4 h = reinterpret_cast<const float4*>(Hin)[(size_t)row * 32 + lane];
    float4 a = reinterpret_cast<const float4*>(g_agg)[(size_t)row * 32 + lane];

    float4 x;
    x.x = h.x + gelu_exact(a.x);
    x.y = h.y + gelu_exact(a.y);
    x.z = h.z + gelu_exact(a.z);
    x.w = h.w + gelu_exact(a.w);

    float s  = x.x + x.y + x.z + x.w;
    float s2 = x.x * x.x + x.y * x.y + x.z * x.z + x.w * x.w;
    #pragma unroll
    for (int o = 16; o > 0; o >>= 1) {
        s  += __shfl_xor_sync(0xFFFFFFFFu, s,  o);
        s2 += __shfl_xor_sync(0xFFFFFFFFu, s2, o);
    }
    const float mu  = s  * (1.0f / 128.0f);
    const float var = s2 * (1.0f / 128.0f) - mu * mu;
    const float inv = rsqrtf(var + 1e-5f);

    float4 g = reinterpret_cast<const float4*>(gamma)[lane];
    float4 b = reinterpret_cast<const float4*>(beta)[lane];
    float4 o4;
    o4.x = (x.x - mu) * inv * g.x + b.x;
    o4.y = (x.y - mu) * inv * g.y + b.y;
    o4.z = (x.z - mu) * inv * g.z + b.z;
    o4.w = (x.w - mu) * inv * g.w + b.w;
    reinterpret_cast<float4*>(out)[(size_t)row * 32 + lane] = o4;
}

// ---------------------------------------------------------------------------
extern "C" void kernel_launch(void* const* d_in, const int* in_sizes, int n_in,
                              void* d_out, int out_size) {
    const float* H     = (const float*)d_in[0];
    const void*  src   = d_in[1];
    const void*  dst   = d_in[2];
    const float* W     = (const float*)d_in[3];
    const float* gamma = (const float*)d_in[4];
    const float* beta  = (const float*)d_in[5];
    float* out = (float*)d_out;

    detect_kernel<<<1, 1>>>((const int*)src);
    zero_kernel<<<(TOT / 4 + 255) / 256, 256>>>();
    gemm_kernel<<<(ROWS + 63) / 64, 256>>>(H, W);
    scatter_kernel<<<(EE + 7) / 8, 256>>>(src, dst);
    ln_kernel<<<(ROWS + 7) / 8, 256>>>(H, gamma, beta, out);
}

// round 4
// speedup vs baseline: 1.1223x; 1.1223x over previous
#include <cuda_runtime.h>
#include <math.h>

#define BB 2
#define NN 50000
#define DD 128
#define EE 800000
#define ROWS (BB*NN)          // 100000
#define TOT  (BB*NN*DD)       // 12,800,000 floats

// Scratch buffers (device globals; no allocation allowed).
__device__ float g_m[TOT];          // GEMM output m = H @ W
__device__ int   g_count[NN];       // per-dst degree
__device__ int   g_offset[NN + 1];  // CSR offsets
__device__ int   g_pos[NN];         // running cursors for permute
__device__ int   g_srcs[EE];        // src ids sorted by dst
__device__ int   g_idx64;

// ---------------------------------------------------------------------------
// Detect int64 vs int32 indices (values < 50000 => odd 32-bit words all zero
// iff int64 little-endian).
// ---------------------------------------------------------------------------
__global__ void detect_kernel(const int* __restrict__ src_words) {
    int is64 = 1;
    #pragma unroll 1
    for (int i = 0; i < 64; i++) {
        if (src_words[2 * i + 1] != 0) { is64 = 0; break; }
    }
    g_idx64 = is64;
}

// ---------------------------------------------------------------------------
// Zero dst histogram.
// ---------------------------------------------------------------------------
__global__ void zero_count_kernel() {
    int i = blockIdx.x * blockDim.x + threadIdx.x;
    if (i < NN) g_count[i] = 0;
}

// ---------------------------------------------------------------------------
// Histogram of dst.
// ---------------------------------------------------------------------------
__global__ void __launch_bounds__(256) hist_kernel(const void* __restrict__ dstp) {
    int e = blockIdx.x * blockDim.x + threadIdx.x;
    if (e >= EE) return;
    int d = g_idx64 ? (int)reinterpret_cast<const long long*>(dstp)[e]
                    : reinterpret_cast<const int*>(dstp)[e];
    atomicAdd(&g_count[d], 1);
}

// ---------------------------------------------------------------------------
// Exclusive prefix scan over 50000 counts. Single block of 1024 threads;
// each thread serially handles a 49-element chunk, Hillis-Steele over partials.
// ---------------------------------------------------------------------------
__global__ void __launch_bounds__(1024) scan_kernel() {
    __shared__ int part[1024];
    const int T = 1024;
    const int C = (NN + T - 1) / T;  // 49
    const int t = threadIdx.x;
    const int base = t * C;

    int s = 0;
    for (int i = 0; i < C; i++) {
        int idx = base + i;
        if (idx < NN) s += g_count[idx];
    }
    part[t] = s;
    __syncthreads();

    #pragma unroll
    for (int off = 1; off < T; off <<= 1) {
        int v = (t >= off) ? part[t - off] : 0;
        __syncthreads();
        part[t] += v;
        __syncthreads();
    }
    int run = part[t] - s;  // exclusive prefix of this chunk

    for (int i = 0; i < C; i++) {
        int idx = base + i;
        if (idx < NN) {
            g_offset[idx] = run;
            g_pos[idx]    = run;
            run += g_count[idx];
        }
    }
    if (t == T - 1) g_offset[NN] = run;
}

// ---------------------------------------------------------------------------
// Permute: bucket src ids by dst.
// ---------------------------------------------------------------------------
__global__ void __launch_bounds__(256) permute_kernel(
    const void* __restrict__ srcp, const void* __restrict__ dstp)
{
    int e = blockIdx.x * blockDim.x + threadIdx.x;
    if (e >= EE) return;
    int s, d;
    if (g_idx64) {
        s = (int)reinterpret_cast<const long long*>(srcp)[e];
        d = (int)reinterpret_cast<const long long*>(dstp)[e];
    } else {
        s = reinterpret_cast<const int*>(srcp)[e];
        d = reinterpret_cast<const int*>(dstp)[e];
    }
    int p = atomicAdd(&g_pos[d], 1);
    g_srcs[p] = s;
}

// ---------------------------------------------------------------------------
// GEMM: m[r, :] = H[r, :] @ W. 256 threads, 64 rows x 128 cols per block.
// k-tiled by 4: per 4 k's a thread does 8 LDS.128 (H) + 4 LDG.128 (W) + 128 FFMA.
// ---------------------------------------------------------------------------
__global__ void __launch_bounds__(256) gemm_kernel(
    const float* __restrict__ H, const float* __restrict__ W)
{
    __shared__ float shH[64][128];
    const int row0 = blockIdx.x * 64;
    const int t = threadIdx.x;

    #pragma unroll
    for (int i = t; i < 64 * 32; i += 256) {
        int r = i >> 5, c4 = i & 31;
        int gr = row0 + r;
        float4 v = (gr < ROWS) ? reinterpret_cast<const float4*>(H)[(size_t)gr * 32 + c4]
                               : make_float4(0.f, 0.f, 0.f, 0.f);
        reinterpret_cast<float4*>(&shH[r][0])[c4] = v;
    }
    __syncthreads();

    const int cg = t & 31;   // col group (4 cols)
    const int rg = t >> 5;   // row group (8 rows)

    float4 acc[8];
    #pragma unroll
    for (int r = 0; r < 8; r++) acc[r] = make_float4(0.f, 0.f, 0.f, 0.f);

    const float4* W4 = reinterpret_cast<const float4*>(W);
    #pragma unroll 2
    for (int k0 = 0; k0 < 128; k0 += 4) {
        float4 w0 = W4[(k0 + 0) * 32 + cg];
        float4 w1 = W4[(k0 + 1) * 32 + cg];
        float4 w2 = W4[(k0 + 2) * 32 + cg];
        float4 w3 = W4[(k0 + 3) * 32 + cg];
        #pragma unroll
        for (int r = 0; r < 8; r++) {
            float4 h = *reinterpret_cast<const float4*>(&shH[rg * 8 + r][k0]);
            acc[r].x = fmaf(h.x, w0.x, acc[r].x);
            acc[r].y = fmaf(h.x, w0.y, acc[r].y);
            acc[r].z = fmaf(h.x, w0.z, acc[r].z);
            acc[r].w = fmaf(h.x, w0.w, acc[r].w);
            acc[r].x = fmaf(h.y, w1.x, acc[r].x);
            acc[r].y = fmaf(h.y, w1.y, acc[r].y);
            acc[r].z = fmaf(h.y, w1.z, acc[r].z);
            acc[r].w = fmaf(h.y, w1.w, acc[r].w);
            acc[r].x = fmaf(h.z, w2.x, acc[r].x);
            acc[r].y = fmaf(h.z, w2.y, acc[r].y);
            acc[r].z = fmaf(h.z, w2.z, acc[r].z);
            acc[r].w = fmaf(h.z, w2.w, acc[r].w);
            acc[r].x = fmaf(h.w, w3.x, acc[r].x);
            acc[r].y = fmaf(h.w, w3.y, acc[r].y);
            acc[r].z = fmaf(h.w, w3.z, acc[r].z);
            acc[r].w = fmaf(h.w, w3.w, acc[r].w);
        }
    }

    #pragma unroll
    for (int r = 0; r < 8; r++) {
        int gr = row0 + rg * 8 + r;
        if (gr < ROWS)
            reinterpret_cast<float4*>(g_m)[(size_t)gr * 32 + cg] = acc[r];
    }
}

// ---------------------------------------------------------------------------
// Fused gather + gelu + LayerNorm. Warp per node; both batches per warp.
//   agg[b] = sum over incoming edges of m[b, src, :]
//   out[b, n, :] = LN(H[b, n, :] + gelu(agg[b]))
// ---------------------------------------------------------------------------
__device__ __forceinline__ float gelu_exact(float v) {
    return 0.5f * v * (1.0f + erff(v * 0.70710678118654752f));
}

__device__ __forceinline__ void acc4(float4& a, const float4& v) {
    a.x += v.x; a.y += v.y; a.z += v.z; a.w += v.w;
}

__global__ void __launch_bounds__(256) fused_kernel(
    const float* __restrict__ Hin,
    const float* __restrict__ gamma, const float* __restrict__ beta,
    float* __restrict__ out)
{
    int n = blockIdx.x * 8 + (threadIdx.x >> 5);
    if (n >= NN) return;
    const int lane = threadIdx.x & 31;

    const int beg = g_offset[n];
    const int end = g_offset[n + 1];

    const float4* m4 = reinterpret_cast<const float4*>(g_m);
    float4 a0 = make_float4(0.f, 0.f, 0.f, 0.f);
    float4 a1 = make_float4(0.f, 0.f, 0.f, 0.f);

    int j = beg;
    for (; j + 4 <= end; j += 4) {
        int s0 = g_srcs[j + 0];
        int s1 = g_srcs[j + 1];
        int s2 = g_srcs[j + 2];
        int s3 = g_srcs[j + 3];
        float4 v00 = m4[(size_t)s0 * 32 + lane];
        float4 v10 = m4[(size_t)s1 * 32 + lane];
        float4 v20 = m4[(size_t)s2 * 32 + lane];
        float4 v30 = m4[(size_t)s3 * 32 + lane];
        float4 v01 = m4[((size_t)NN + s0) * 32 + lane];
        float4 v11 = m4[((size_t)NN + s1) * 32 + lane];
        float4 v21 = m4[((size_t)NN + s2) * 32 + lane];
        float4 v31 = m4[((size_t)NN + s3) * 32 + lane];
        acc4(a0, v00); acc4(a0, v10); acc4(a0, v20); acc4(a0, v30);
        acc4(a1, v01); acc4(a1, v11); acc4(a1, v21); acc4(a1, v31);
    }
    for (; j < end; j++) {
        int s = g_srcs[j];
        acc4(a0, m4[(size_t)s * 32 + lane]);
        acc4(a1, m4[((size_t)NN + s) * 32 + lane]);
    }

    const float4 g = reinterpret_cast<const float4*>(gamma)[lane];
    const float4 b = reinterpret_cast<const float4*>(beta)[lane];

    #pragma unroll
    for (int bb = 0; bb < BB; bb++) {
        const size_t row = (size_t)bb * NN + n;
        const float4 a = (bb == 0) ? a0 : a1;
        float4 h = reinterpret_cast<const float4*>(Hin)[row * 32 + lane];
        float4 x;
        x.x = h.x + gelu_exact(a.x);
        x.y = h.y + gelu_exact(a.y);
        x.z = h.z + gelu_exact(a.z);
        x.w = h.w + gelu_exact(a.w);

        float s  = x.x + x.y + x.z + x.w;
        float s2 = x.x * x.x + x.y * x.y + x.z * x.z + x.w * x.w;
        #pragma unroll
        for (int o = 16; o > 0; o >>= 1) {
            s  += __shfl_xor_sync(0xFFFFFFFFu, s,  o);
            s2 += __shfl_xor_sync(0xFFFFFFFFu, s2, o);
        }
        const float mu  = s * (1.0f / 128.0f);
        const float var = s2 * (1.0f / 128.0f) - mu * mu;
        const float inv = rsqrtf(var + 1e-5f);

        float4 o4;
        o4.x = (x.x - mu) * inv * g.x + b.x;
        o4.y = (x.y - mu) * inv * g.y + b.y;
        o4.z = (x.z - mu) * inv * g.z + b.z;
        o4.w = (x.w - mu) * inv * g.w + b.w;
        reinterpret_cast<float4*>(out)[row * 32 + lane] = o4;
    }
}

// ---------------------------------------------------------------------------
extern "C" void kernel_launch(void* const* d_in, const int* in_sizes, int n_in,
                              void* d_out, int out_size) {
    const float* H     = (const float*)d_in[0];
    const void*  src   = d_in[1];
    const void*  dst   = d_in[2];
    const float* W     = (const float*)d_in[3];
    const float* gamma = (const float*)d_in[4];
    const float* beta  = (const float*)d_in[5];
    float* out = (float*)d_out;

    detect_kernel<<<1, 1>>>((const int*)src);
    zero_count_kernel<<<(NN + 255) / 256, 256>>>();
    hist_kernel<<<(EE + 255) / 256, 256>>>(dst);
    scan_kernel<<<1, 1024>>>();
    permute_kernel<<<(EE + 255) / 256, 256>>>(src, dst);
    gemm_kernel<<<(ROWS + 63) / 64, 256>>>(H, W);
    fused_kernel<<<(NN + 7) / 8, 256>>>(H, gamma, beta, out);
}

// round 7
// speedup vs baseline: 1.5982x; 1.4240x over previous
#include <cuda_runtime.h>
#include <math.h>

#define BB 2
#define NN 50000
#define DD 128
#define EE 800000
#define ROWS (BB*NN)          // 100000
#define TOT  (BB*NN*DD)       // 12,800,000 floats

#define TILE 2048             // elements per scan block
#define NTILES ((NN + TILE - 1) / TILE)   // 25

// Scratch buffers (device globals; no allocation allowed).
__device__ float g_m[TOT];          // GEMM output m = H @ W
__device__ int   g_count[NN];       // per-dst degree
__device__ int   g_offset[NN + 1];  // CSR offsets
__device__ int   g_pos[NN];         // running cursors for permute
__device__ int   g_srcs[EE];        // src ids sorted by dst
__device__ int   g_bsum[NTILES];    // per-tile totals
__device__ int   g_bofs[NTILES];    // exclusive scan of tile totals
__device__ int   g_idx64;

// ---------------------------------------------------------------------------
// Detect int64 vs int32 indices with one warp + ballot. For int64 (values
// < 50000, little-endian) every odd 32-bit word is zero; for int32 random
// index data the odd words are index values (nonzero w.h.p. across 32).
// ---------------------------------------------------------------------------
__global__ void detect_kernel(const int* __restrict__ src_words) {
    int lane = threadIdx.x;
    int w = src_words[2 * lane + 1];
    unsigned nz = __ballot_sync(0xFFFFFFFFu, w != 0);
    if (lane == 0) g_idx64 = (nz == 0u);
}

// ---------------------------------------------------------------------------
// Zero dst histogram.
// ---------------------------------------------------------------------------
__global__ void zero_count_kernel() {
    int i = blockIdx.x * blockDim.x + threadIdx.x;
    if (i < NN) g_count[i] = 0;
}

// ---------------------------------------------------------------------------
// Histogram of dst.
// ---------------------------------------------------------------------------
__global__ void __launch_bounds__(256) hist_kernel(const void* __restrict__ dstp) {
    int e = blockIdx.x * blockDim.x + threadIdx.x;
    if (e >= EE) return;
    int d = g_idx64 ? (int)reinterpret_cast<const long long*>(dstp)[e]
                    : reinterpret_cast<const int*>(dstp)[e];
    atomicAdd(&g_count[d], 1);
}

// ---------------------------------------------------------------------------
// Scan phase 1: per-tile exclusive scan (1024 threads, 2 elements/thread),
// local prefixes into g_offset, tile total into g_bsum.
// ---------------------------------------------------------------------------
__global__ void __launch_bounds__(1024) scan1_kernel() {
    __shared__ int warp_base[32];
    const int tid  = threadIdx.x;
    const int lane = tid & 31;
    const int wid  = tid >> 5;
    const int idx  = blockIdx.x * TILE + 2 * tid;

    int a = (idx     < NN) ? g_count[idx]     : 0;
    int b = (idx + 1 < NN) ? g_count[idx + 1] : 0;
    int s = a + b;

    // inclusive warp scan of s
    int incl = s;
    #pragma unroll
    for (int o = 1; o < 32; o <<= 1) {
        int v = __shfl_up_sync(0xFFFFFFFFu, incl, o);
        if (lane >= o) incl += v;
    }
    if (lane == 31) warp_base[wid] = incl;   // warp totals (inclusive)
    __syncthreads();

    if (wid == 0) {
        int t = warp_base[lane];
        int ti = t;
        #pragma unroll
        for (int o = 1; o < 32; o <<= 1) {
            int v = __shfl_up_sync(0xFFFFFFFFu, ti, o);
            if (lane >= o) ti += v;
        }
        warp_base[lane] = ti - t;            // exclusive warp bases
    }
    __syncthreads();

    int p = warp_base[wid] + incl - s;       // exclusive prefix of this pair
    if (idx     < NN) g_offset[idx]     = p;
    if (idx + 1 < NN) g_offset[idx + 1] = p + a;
    if (tid == 1023) g_bsum[blockIdx.x] = p + s;  // tile total
}

// ---------------------------------------------------------------------------
// Scan phase 2: exclusive scan of NTILES (=25) tile totals, one warp.
// ---------------------------------------------------------------------------
__global__ void scan2_kernel() {
    int lane = threadIdx.x;
    int t = (lane < NTILES) ? g_bsum[lane] : 0;
    int ti = t;
    #pragma unroll
    for (int o = 1; o < 32; o <<= 1) {
        int v = __shfl_up_sync(0xFFFFFFFFu, ti, o);
        if (lane >= o) ti += v;
    }
    if (lane < NTILES) g_bofs[lane] = ti - t;
}

// ---------------------------------------------------------------------------
// Scan phase 3: add tile offsets; mirror into g_pos; set g_offset[NN] = EE.
// ---------------------------------------------------------------------------
__global__ void __launch_bounds__(256) scan3_kernel() {
    int i = blockIdx.x * blockDim.x + threadIdx.x;
    if (i < NN) {
        int o = g_offset[i] + g_bofs[i / TILE];
        g_offset[i] = o;
        g_pos[i]    = o;
    } else if (i == NN) {
        g_offset[NN] = EE;
    }
}

// ---------------------------------------------------------------------------
// Permute: bucket src ids by dst.
// ---------------------------------------------------------------------------
__global__ void __launch_bounds__(256) permute_kernel(
    const void* __restrict__ srcp, const void* __restrict__ dstp)
{
    int e = blockIdx.x * blockDim.x + threadIdx.x;
    if (e >= EE) return;
    int s, d;
    if (g_idx64) {
        s = (int)reinterpret_cast<const long long*>(srcp)[e];
        d = (int)reinterpret_cast<const long long*>(dstp)[e];
    } else {
        s = reinterpret_cast<const int*>(srcp)[e];
        d = reinterpret_cast<const int*>(dstp)[e];
    }
    int p = atomicAdd(&g_pos[d], 1);
    g_srcs[p] = s;
}

// ---------------------------------------------------------------------------
// GEMM: m[r, :] = H[r, :] @ W. 256 threads, 64 rows x 128 cols per block.
// ---------------------------------------------------------------------------
__global__ void __launch_bounds__(256) gemm_kernel(
    const float* __restrict__ H, const float* __restrict__ W)
{
    __shared__ float shH[64][128];
    const int row0 = blockIdx.x * 64;
    const int t = threadIdx.x;

    #pragma unroll
    for (int i = t; i < 64 * 32; i += 256) {
        int r = i >> 5, c4 = i & 31;
        int gr = row0 + r;
        float4 v = (gr < ROWS) ? reinterpret_cast<const float4*>(H)[(size_t)gr * 32 + c4]
                               : make_float4(0.f, 0.f, 0.f, 0.f);
        reinterpret_cast<float4*>(&shH[r][0])[c4] = v;
    }
    __syncthreads();

    const int cg = t & 31;
    const int rg = t >> 5;

    float4 acc[8];
    #pragma unroll
    for (int r = 0; r < 8; r++) acc[r] = make_float4(0.f, 0.f, 0.f, 0.f);

    const float4* W4 = reinterpret_cast<const float4*>(W);
    #pragma unroll 2
    for (int k0 = 0; k0 < 128; k0 += 4) {
        float4 w0 = W4[(k0 + 0) * 32 + cg];
        float4 w1 = W4[(k0 + 1) * 32 + cg];
        float4 w2 = W4[(k0 + 2) * 32 + cg];
        float4 w3 = W4[(k0 + 3) * 32 + cg];
        #pragma unroll
        for (int r = 0; r < 8; r++) {
            float4 h = *reinterpret_cast<const float4*>(&shH[rg * 8 + r][k0]);
            acc[r].x = fmaf(h.x, w0.x, acc[r].x);
            acc[r].y = fmaf(h.x, w0.y, acc[r].y);
            acc[r].z = fmaf(h.x, w0.z, acc[r].z);
            acc[r].w = fmaf(h.x, w0.w, acc[r].w);
            acc[r].x = fmaf(h.y, w1.x, acc[r].x);
            acc[r].y = fmaf(h.y, w1.y, acc[r].y);
            acc[r].z = fmaf(h.y, w1.z, acc[r].z);
            acc[r].w = fmaf(h.y, w1.w, acc[r].w);
            acc[r].x = fmaf(h.z, w2.x, acc[r].x);
            acc[r].y = fmaf(h.z, w2.y, acc[r].y);
            acc[r].z = fmaf(h.z, w2.z, acc[r].z);
            acc[r].w = fmaf(h.z, w2.w, acc[r].w);
            acc[r].x = fmaf(h.w, w3.x, acc[r].x);
            acc[r].y = fmaf(h.w, w3.y, acc[r].y);
            acc[r].z = fmaf(h.w, w3.z, acc[r].z);
            acc[r].w = fmaf(h.w, w3.w, acc[r].w);
        }
    }

    #pragma unroll
    for (int r = 0; r < 8; r++) {
        int gr = row0 + rg * 8 + r;
        if (gr < ROWS)
            reinterpret_cast<float4*>(g_m)[(size_t)gr * 32 + cg] = acc[r];
    }
}

// ---------------------------------------------------------------------------
// Fused gather + gelu + LayerNorm. Warp per node; both batches per warp.
// ---------------------------------------------------------------------------
__device__ __forceinline__ float gelu_exact(float v) {
    return 0.5f * v * (1.0f + erff(v * 0.70710678118654752f));
}

__device__ __forceinline__ void acc4(float4& a, const float4& v) {
    a.x += v.x; a.y += v.y; a.z += v.z; a.w += v.w;
}

__global__ void __launch_bounds__(256) fused_kernel(
    const float* __restrict__ Hin,
    const float* __restrict__ gamma, const float* __restrict__ beta,
    float* __restrict__ out)
{
    int n = blockIdx.x * 8 + (threadIdx.x >> 5);
    if (n >= NN) return;
    const int lane = threadIdx.x & 31;

    const int beg = g_offset[n];
    const int end = g_offset[n + 1];

    const float4* m4 = reinterpret_cast<const float4*>(g_m);
    float4 a0 = make_float4(0.f, 0.f, 0.f, 0.f);
    float4 a1 = make_float4(0.f, 0.f, 0.f, 0.f);

    int j = beg;
    for (; j + 4 <= end; j += 4) {
        int s0 = g_srcs[j + 0];
        int s1 = g_srcs[j + 1];
        int s2 = g_srcs[j + 2];
        int s3 = g_srcs[j + 3];
        float4 v00 = m4[(size_t)s0 * 32 + lane];
        float4 v10 = m4[(size_t)s1 * 32 + lane];
        float4 v20 = m4[(size_t)s2 * 32 + lane];
        float4 v30 = m4[(size_t)s3 * 32 + lane];
        float4 v01 = m4[((size_t)NN + s0) * 32 + lane];
        float4 v11 = m4[((size_t)NN + s1) * 32 + lane];
        float4 v21 = m4[((size_t)NN + s2) * 32 + lane];
        float4 v31 = m4[((size_t)NN + s3) * 32 + lane];
        acc4(a0, v00); acc4(a0, v10); acc4(a0, v20); acc4(a0, v30);
        acc4(a1, v01); acc4(a1, v11); acc4(a1, v21); acc4(a1, v31);
    }
    for (; j < end; j++) {
        int s = g_srcs[j];
        acc4(a0, m4[(size_t)s * 32 + lane]);
        acc4(a1, m4[((size_t)NN + s) * 32 + lane]);
    }

    const float4 g = reinterpret_cast<const float4*>(gamma)[lane];
    const float4 b = reinterpret_cast<const float4*>(beta)[lane];

    #pragma unroll
    for (int bb = 0; bb < BB; bb++) {
        const size_t row = (size_t)bb * NN + n;
        const float4 a = (bb == 0) ? a0 : a1;
        float4 h = reinterpret_cast<const float4*>(Hin)[row * 32 + lane];
        float4 x;
        x.x = h.x + gelu_exact(a.x);
        x.y = h.y + gelu_exact(a.y);
        x.z = h.z + gelu_exact(a.z);
        x.w = h.w + gelu_exact(a.w);

        float s  = x.x + x.y + x.z + x.w;
        float s2 = x.x * x.x + x.y * x.y + x.z * x.z + x.w * x.w;
        #pragma unroll
        for (int o = 16; o > 0; o >>= 1) {
            s  += __shfl_xor_sync(0xFFFFFFFFu, s,  o);
            s2 += __shfl_xor_sync(0xFFFFFFFFu, s2, o);
        }
        const float mu  = s * (1.0f / 128.0f);
        const float var = s2 * (1.0f / 128.0f) - mu * mu;
        const float inv = rsqrtf(var + 1e-5f);

        float4 o4;
        o4.x = (x.x - mu) * inv * g.x + b.x;
        o4.y = (x.y - mu) * inv * g.y + b.y;
        o4.z = (x.z - mu) * inv * g.z + b.z;
        o4.w = (x.w - mu) * inv * g.w + b.w;
        reinterpret_cast<float4*>(out)[row * 32 + lane] = o4;
    }
}

// ---------------------------------------------------------------------------
extern "C" void kernel_launch(void* const* d_in, const int* in_sizes, int n_in,
                              void* d_out, int out_size) {
    const float* H     = (const float*)d_in[0];
    const void*  src   = d_in[1];
    const void*  dst   = d_in[2];
    const float* W     = (const float*)d_in[3];
    const float* gamma = (const float*)d_in[4];
    const float* beta  = (const float*)d_in[5];
    float* out = (float*)d_out;

    detect_kernel<<<1, 32>>>((const int*)src);
    zero_count_kernel<<<(NN + 255) / 256, 256>>>();
    hist_kernel<<<(EE + 255) / 256, 256>>>(dst);
    scan1_kernel<<<NTILES, 1024>>>();
    scan2_kernel<<<1, 32>>>();
    scan3_kernel<<<(NN + 256) / 256, 256>>>();
    permute_kernel<<<(EE + 255) / 256, 256>>>(src, dst);
    gemm_kernel<<<(ROWS + 63) / 64, 256>>>(H, W);
    fused_kernel<<<(NN + 7) / 8, 256>>>(H, gamma, beta, out);
}